// round 3
// baseline (speedup 1.0000x reference)
#include <cuda_runtime.h>
#include <cstdint>

// Instant-NGP fused forward: 16-level 2D hashgrid encode + MLP 32->64->64->3 (ReLU)
// R3: weights moved to __constant__ memory. All weight reads are warp-uniform with
// compile-time offsets -> LDC/LDCU on the constant port, freeing the L1/shared pipe
// for the hash-table gathers (previously 88.9% L1 throughput, dominated by broadcast
// LDS.128 weight reads delivering only 16B/wavefront).

constexpr int NLV = 16;
constexpr int TSZ = 1 << 19;           // 524288 entries per level
constexpr unsigned PRIME_Y = 2654435761u;

__constant__ float cW1[32 * 64];
__constant__ float cW2[64 * 64];
__constant__ float cW3[64 * 3];

__global__ __launch_bounds__(128, 5) void ngp_fused(
    const float* __restrict__ pos,      // [N,2]
    const float* __restrict__ table,    // [16, TSZ, 2]
    float* __restrict__ out,            // [N,3]
    int n)
{
    int idx = blockIdx.x * 128 + threadIdx.x;
    if (idx >= n) return;

    const float2 p = ((const float2*)pos)[idx];

    // ---- hash-grid encode, layer-1 folded in: h1[j] = sum_lvl f*W1row ----
    float h1[64];
#pragma unroll
    for (int j = 0; j < 64; j++) h1[j] = 0.f;

#pragma unroll
    for (int lvl = 0; lvl < NLV; lvl++) {
        const int res = 16 << lvl;                 // ceil(scale)+1, scale integer
        const float scale = (float)(res - 1);      // BASE_RES*2^lvl - 1, exact fp32
        float px = p.x * scale + 0.5f;
        float py = p.y * scale + 0.5f;
        float fx = floorf(px), fy = floorf(py);
        float wx = px - fx,    wy = py - fy;
        unsigned cx = (unsigned)fx, cy = (unsigned)fy;

        unsigned i00, i10, i01, i11;
        if ((long long)res * res <= TSZ) {         // dense (compile-time per level)
            i00 = cx + cy * (unsigned)res;
            i10 = i00 + 1u;
            i01 = i00 + (unsigned)res;
            i11 = i01 + 1u;
        } else {                                   // tcnn spatial hash
            unsigned hy0 = cy * PRIME_Y;
            unsigned hy1 = (cy + 1u) * PRIME_Y;
            i00 = (cx        ^ hy0) & (unsigned)(TSZ - 1);
            i10 = ((cx + 1u) ^ hy0) & (unsigned)(TSZ - 1);
            i01 = (cx        ^ hy1) & (unsigned)(TSZ - 1);
            i11 = ((cx + 1u) ^ hy1) & (unsigned)(TSZ - 1);
        }

        const float2* tl = (const float2*)table + (size_t)lvl * TSZ;
        float2 v00 = __ldg(tl + i00);
        float2 v10 = __ldg(tl + i10);
        float2 v01 = __ldg(tl + i01);
        float2 v11 = __ldg(tl + i11);

        float w00 = (1.f - wx) * (1.f - wy);
        float w10 = wx * (1.f - wy);
        float w01 = (1.f - wx) * wy;
        float w11 = wx * wy;

        float f0 = w00 * v00.x + w10 * v10.x + w01 * v01.x + w11 * v11.x;
        float f1 = w00 * v00.y + w10 * v10.y + w01 * v01.y + w11 * v11.y;

        // fold into layer 1 immediately (feat never stored); weight offsets are
        // compile-time constants -> constant-port loads
#pragma unroll
        for (int j = 0; j < 16; j++) {
            float4 a = *(const float4*)(cW1 + (2 * lvl + 0) * 64 + 4 * j);
            float4 b = *(const float4*)(cW1 + (2 * lvl + 1) * 64 + 4 * j);
            h1[4 * j + 0] += f0 * a.x + f1 * b.x;
            h1[4 * j + 1] += f0 * a.y + f1 * b.y;
            h1[4 * j + 2] += f0 * a.z + f1 * b.z;
            h1[4 * j + 3] += f0 * a.w + f1 * b.w;
        }
    }

#pragma unroll
    for (int j = 0; j < 64; j++) h1[j] = fmaxf(h1[j], 0.f);

    // ---- layer 2 (chunks of 8) with layer 3 folded in; h2 never stored ----
    float o0 = 0.f, o1 = 0.f, o2 = 0.f;
#pragma unroll
    for (int jc = 0; jc < 8; jc++) {
        float c[8];
#pragma unroll
        for (int k = 0; k < 8; k++) c[k] = 0.f;
#pragma unroll
        for (int i = 0; i < 64; i++) {
            float f = h1[i];
            float4 a = *(const float4*)(cW2 + i * 64 + jc * 8);
            float4 b = *(const float4*)(cW2 + i * 64 + jc * 8 + 4);
            c[0] += f * a.x; c[1] += f * a.y; c[2] += f * a.z; c[3] += f * a.w;
            c[4] += f * b.x; c[5] += f * b.y; c[6] += f * b.z; c[7] += f * b.w;
        }
#pragma unroll
        for (int k = 0; k < 8; k++) {
            float h = fmaxf(c[k], 0.f);
            int j = jc * 8 + k;
            o0 += h * cW3[j * 3 + 0];
            o1 += h * cW3[j * 3 + 1];
            o2 += h * cW3[j * 3 + 2];
        }
    }

    out[idx * 3 + 0] = o0;
    out[idx * 3 + 1] = o1;
    out[idx * 3 + 2] = o2;
}

extern "C" void kernel_launch(void* const* d_in, const int* in_sizes, int n_in,
                              void* d_out, int out_size) {
    const float* pos   = (const float*)d_in[0];
    const float* table = (const float*)d_in[1];

    // Stage weights into constant memory (async D2D memcpy nodes; graph-capturable)
    cudaMemcpyToSymbolAsync(cW1, d_in[2], 32 * 64 * sizeof(float), 0,
                            cudaMemcpyDeviceToDevice, 0);
    cudaMemcpyToSymbolAsync(cW2, d_in[3], 64 * 64 * sizeof(float), 0,
                            cudaMemcpyDeviceToDevice, 0);
    cudaMemcpyToSymbolAsync(cW3, d_in[4], 64 * 3 * sizeof(float), 0,
                            cudaMemcpyDeviceToDevice, 0);

    float* out = (float*)d_out;
    int n = in_sizes[0] / 2;
    int blocks = (n + 127) / 128;
    ngp_fused<<<blocks, 128>>>(pos, table, out, n);
}

// round 4
// speedup vs baseline: 1.5290x; 1.5290x over previous
#include <cuda_runtime.h>
#include <cstdint>

// Instant-NGP fused forward, R4: tensor-core MLP (mma.sync m16n8k8 tf32).
// CTA = 128 threads = 4 independent warps; each warp owns 32 points.
// encode (scalar, gathers) -> sA[128x32] -> GEMM1 tensor -> sC[128x64]
// -> GEMM2 tensor -> layer3 scalar in regs + quad-shuffle reduce -> out.
// sA and sC alias one smem buffer (sA dead after GEMM1 k-loop; one CTA sync
// separates all sA reads from sC writes). W2 staged in smem at stride 68 so
// b-fragment LDS are conflict-free.

constexpr int NLV = 16;
constexpr int TSZ = 1 << 19;
constexpr unsigned PRIME_Y = 2654435761u;

constexpr int SA_STR  = 33;   // feats: conflict-free encode stores
constexpr int SC_STR  = 68;   // activations: conflict-free A-frag loads (4g+c distinct)
constexpr int SW2_STR = 68;   // staged W2: conflict-free B-frag loads
constexpr int SMEM_BYTES = (128 * SC_STR + 64 * SW2_STR) * 4;   // 52224 B

__device__ __forceinline__ uint32_t f2tf(float f) {
    uint32_t u; asm("cvt.rna.tf32.f32 %0, %1;" : "=r"(u) : "f"(f)); return u;
}

__device__ __forceinline__ void mma8(float c[4], const uint32_t a[4], const uint32_t b[2]) {
    asm volatile("mma.sync.aligned.m16n8k8.row.col.f32.tf32.tf32.f32 "
                 "{%0,%1,%2,%3},{%4,%5,%6,%7},{%8,%9},{%0,%1,%2,%3};"
                 : "+f"(c[0]), "+f"(c[1]), "+f"(c[2]), "+f"(c[3])
                 : "r"(a[0]), "r"(a[1]), "r"(a[2]), "r"(a[3]), "r"(b[0]), "r"(b[1]));
}

__global__ __launch_bounds__(128, 4) void ngp_tc(
    const float* __restrict__ pos,      // [N,2]
    const float* __restrict__ table,    // [16, TSZ, 2]
    const float* __restrict__ W1,       // [32,64]
    const float* __restrict__ W2,       // [64,64]
    const float* __restrict__ W3,       // [64,3]
    float* __restrict__ out,            // [N,3]
    int n)
{
    extern __shared__ float sm[];
    float* sAct = sm;                       // union: sA [128][33] then sC [128][68]
    float* sW2  = sm + 128 * SC_STR;        // [64][68]

    const int t    = threadIdx.x;
    const int lane = t & 31;
    const int warp = t >> 5;
    const int m0   = warp * 32;
    const int g    = lane >> 2;             // groupID (0..7)
    const int q    = lane & 3;              // tid-in-group (0..3)
    const int base = blockIdx.x * 128;
    const int idx  = base + t;

    // ---- stage W2 into smem (tf32-rounded), coalesced ----
    for (int i = t; i < 64 * 64; i += 128) {
        int k = i >> 6, c = i & 63;
        sW2[k * SW2_STR + c] = __uint_as_float(f2tf(W2[i]));
    }

    // ---- encode: feats -> sA[t][0..31] (tf32-rounded) ----
    {
        float2 p = (idx < n) ? ((const float2*)pos)[idx] : make_float2(0.f, 0.f);
#pragma unroll
        for (int lvl = 0; lvl < NLV; lvl++) {
            const int res = 16 << lvl;
            const float scale = (float)(res - 1);
            float px = p.x * scale + 0.5f;
            float py = p.y * scale + 0.5f;
            float fx = floorf(px), fy = floorf(py);
            float wx = px - fx,    wy = py - fy;
            unsigned cx = (unsigned)fx, cy = (unsigned)fy;

            unsigned i00, i10, i01, i11;
            if ((long long)res * res <= TSZ) {
                i00 = cx + cy * (unsigned)res;
                i10 = i00 + 1u;
                i01 = i00 + (unsigned)res;
                i11 = i01 + 1u;
            } else {
                unsigned hy0 = cy * PRIME_Y;
                unsigned hy1 = (cy + 1u) * PRIME_Y;
                i00 = (cx        ^ hy0) & (unsigned)(TSZ - 1);
                i10 = ((cx + 1u) ^ hy0) & (unsigned)(TSZ - 1);
                i01 = (cx        ^ hy1) & (unsigned)(TSZ - 1);
                i11 = ((cx + 1u) ^ hy1) & (unsigned)(TSZ - 1);
            }

            const float2* tl = (const float2*)table + (size_t)lvl * TSZ;
            float2 v00 = __ldg(tl + i00);
            float2 v10 = __ldg(tl + i10);
            float2 v01 = __ldg(tl + i01);
            float2 v11 = __ldg(tl + i11);

            float w00 = (1.f - wx) * (1.f - wy);
            float w10 = wx * (1.f - wy);
            float w01 = (1.f - wx) * wy;
            float w11 = wx * wy;

            float f0 = w00 * v00.x + w10 * v10.x + w01 * v01.x + w11 * v11.x;
            float f1 = w00 * v00.y + w10 * v10.y + w01 * v01.y + w11 * v11.y;

            sAct[t * SA_STR + 2 * lvl + 0] = __uint_as_float(f2tf(f0));
            sAct[t * SA_STR + 2 * lvl + 1] = __uint_as_float(f2tf(f1));
        }
    }
    __syncwarp();

    // ---- GEMM1: C1[32x64] = A[32x32] @ W1[32x64]  (warp-local rows) ----
    float acc[2][8][4];
#pragma unroll
    for (int mt = 0; mt < 2; mt++)
#pragma unroll
        for (int nt = 0; nt < 8; nt++)
#pragma unroll
            for (int r = 0; r < 4; r++) acc[mt][nt][r] = 0.f;

#pragma unroll
    for (int k0 = 0; k0 < 32; k0 += 8) {
        uint32_t a[2][4];
#pragma unroll
        for (int mt = 0; mt < 2; mt++) {
            int r = m0 + mt * 16 + g;
            a[mt][0] = __float_as_uint(sAct[r * SA_STR + k0 + q]);
            a[mt][1] = __float_as_uint(sAct[(r + 8) * SA_STR + k0 + q]);
            a[mt][2] = __float_as_uint(sAct[r * SA_STR + k0 + q + 4]);
            a[mt][3] = __float_as_uint(sAct[(r + 8) * SA_STR + k0 + q + 4]);
        }
#pragma unroll
        for (int nt = 0; nt < 8; nt++) {
            uint32_t b[2];
            b[0] = f2tf(__ldg(&W1[(k0 + q)     * 64 + nt * 8 + g]));
            b[1] = f2tf(__ldg(&W1[(k0 + q + 4) * 64 + nt * 8 + g]));
            mma8(acc[0][nt], a[0], b);
            mma8(acc[1][nt], a[1], b);
        }
    }

    // all warps must finish reading sA before anyone overwrites it as sC
    __syncthreads();

    // ---- ReLU + store C1 (tf32-rounded) ----
#pragma unroll
    for (int mt = 0; mt < 2; mt++) {
        int r = m0 + mt * 16 + g;
#pragma unroll
        for (int nt = 0; nt < 8; nt++) {
            int c = nt * 8 + 2 * q;
            sAct[r * SC_STR + c]           = __uint_as_float(f2tf(fmaxf(acc[mt][nt][0], 0.f)));
            sAct[r * SC_STR + c + 1]       = __uint_as_float(f2tf(fmaxf(acc[mt][nt][1], 0.f)));
            sAct[(r + 8) * SC_STR + c]     = __uint_as_float(f2tf(fmaxf(acc[mt][nt][2], 0.f)));
            sAct[(r + 8) * SC_STR + c + 1] = __uint_as_float(f2tf(fmaxf(acc[mt][nt][3], 0.f)));
        }
    }
    __syncwarp();

    // ---- GEMM2: C2[32x64] = C1[32x64] @ W2[64x64] ----
    float acc2[2][8][4];
#pragma unroll
    for (int mt = 0; mt < 2; mt++)
#pragma unroll
        for (int nt = 0; nt < 8; nt++)
#pragma unroll
            for (int r = 0; r < 4; r++) acc2[mt][nt][r] = 0.f;

#pragma unroll
    for (int k0 = 0; k0 < 64; k0 += 8) {
        uint32_t a[2][4];
#pragma unroll
        for (int mt = 0; mt < 2; mt++) {
            int r = m0 + mt * 16 + g;
            a[mt][0] = __float_as_uint(sAct[r * SC_STR + k0 + q]);
            a[mt][1] = __float_as_uint(sAct[(r + 8) * SC_STR + k0 + q]);
            a[mt][2] = __float_as_uint(sAct[r * SC_STR + k0 + q + 4]);
            a[mt][3] = __float_as_uint(sAct[(r + 8) * SC_STR + k0 + q + 4]);
        }
#pragma unroll
        for (int nt = 0; nt < 8; nt++) {
            uint32_t b[2];
            b[0] = __float_as_uint(sW2[(k0 + q)     * SW2_STR + nt * 8 + g]);
            b[1] = __float_as_uint(sW2[(k0 + q + 4) * SW2_STR + nt * 8 + g]);
            mma8(acc2[0][nt], a[0], b);
            mma8(acc2[1][nt], a[1], b);
        }
    }

    // ---- epilogue: ReLU + layer3 (scalar fp32) + quad reduce ----
    // lane holds C2 at rows {m0+mt*16+g, +8}, cols {8nt+2q, 8nt+2q+1}
    float o[2][2][3];
#pragma unroll
    for (int mt = 0; mt < 2; mt++)
#pragma unroll
        for (int h = 0; h < 2; h++)
#pragma unroll
            for (int j = 0; j < 3; j++) o[mt][h][j] = 0.f;

#pragma unroll
    for (int nt = 0; nt < 8; nt++) {
        int c0 = nt * 8 + 2 * q;
        float w30[3], w31[3];
#pragma unroll
        for (int j = 0; j < 3; j++) {
            w30[j] = __ldg(&W3[c0 * 3 + j]);
            w31[j] = __ldg(&W3[(c0 + 1) * 3 + j]);
        }
#pragma unroll
        for (int mt = 0; mt < 2; mt++) {
            float v0 = fmaxf(acc2[mt][nt][0], 0.f);
            float v1 = fmaxf(acc2[mt][nt][1], 0.f);
            float v2 = fmaxf(acc2[mt][nt][2], 0.f);
            float v3 = fmaxf(acc2[mt][nt][3], 0.f);
#pragma unroll
            for (int j = 0; j < 3; j++) {
                o[mt][0][j] += v0 * w30[j] + v1 * w31[j];
                o[mt][1][j] += v2 * w30[j] + v3 * w31[j];
            }
        }
    }

    // reduce across the 4 lanes of each quad (they partition the 64 columns)
#pragma unroll
    for (int mt = 0; mt < 2; mt++)
#pragma unroll
        for (int h = 0; h < 2; h++)
#pragma unroll
            for (int j = 0; j < 3; j++) {
                float v = o[mt][h][j];
                v += __shfl_xor_sync(0xffffffffu, v, 1);
                v += __shfl_xor_sync(0xffffffffu, v, 2);
                o[mt][h][j] = v;
            }

    if (q < 3) {
        int j = q;
#pragma unroll
        for (int mt = 0; mt < 2; mt++)
#pragma unroll
            for (int h = 0; h < 2; h++) {
                int row = base + m0 + mt * 16 + g + h * 8;
                if (row < n) out[row * 3 + j] = o[mt][h][j];
            }
    }
}

extern "C" void kernel_launch(void* const* d_in, const int* in_sizes, int n_in,
                              void* d_out, int out_size) {
    const float* pos   = (const float*)d_in[0];
    const float* table = (const float*)d_in[1];
    const float* W1    = (const float*)d_in[2];
    const float* W2    = (const float*)d_in[3];
    const float* W3    = (const float*)d_in[4];
    float* out = (float*)d_out;
    int n = in_sizes[0] / 2;
    int blocks = (n + 127) / 128;

    static bool attr_set = false;
    if (!attr_set) {
        cudaFuncSetAttribute(ngp_tc, cudaFuncAttributeMaxDynamicSharedMemorySize,
                             SMEM_BYTES);
        attr_set = true;
    }
    ngp_tc<<<blocks, 128, SMEM_BYTES>>>(pos, table, W1, W2, W3, out, n);
}